// round 11
// baseline (speedup 1.0000x reference)
#include <cuda_runtime.h>
#include <cuda_fp16.h>
#include <cstdint>

#define N_NODES 50000
#define N_EDGES 1600000
#define IN_DIM  1024
#define MID_DIM 256
#define NBLK_SCAN ((N_NODES + 255) / 256)   // 196

// ---------------- scratch (device globals; no allocs allowed) ----------------
__device__ __align__(16) float  g_dis[N_NODES];
__device__ __align__(16) __half g_w1h [(size_t)IN_DIM * MID_DIM];   // fp16(W1)
__device__ __align__(16) __half g_w2h [(size_t)MID_DIM * IN_DIM];   // fp16(W2)
__device__ __align__(16) __half g_xw  [(size_t)N_NODES * MID_DIM];  // x@W1
__device__ __align__(16) __half g_h   [(size_t)N_NODES * MID_DIM];  // relu(A xw + b1)
__device__ __align__(16) __half g_ag2 [(size_t)N_NODES * MID_DIM];  // A h
__device__ int    g_cnt[N_NODES];
__device__ int    g_rowptr[N_NODES];
__device__ int    g_cur[N_NODES];
__device__ int    g_bsum[NBLK_SCAN];
__device__ __align__(8) float2 g_epack[N_EDGES];  // {src_as_float_bits, norm}
__device__ int    g_is64;

// ---------------- helpers ----------------
__device__ __forceinline__ uint32_t smem_u32(const void* p) {
    uint32_t a;
    asm("{ .reg .u64 t; cvta.to.shared.u64 t, %1; cvt.u32.u64 %0, t; }"
        : "=r"(a) : "l"(p));
    return a;
}
__device__ __forceinline__ void ldmatrix_x4(uint32_t* r, uint32_t addr) {
    asm volatile("ldmatrix.sync.aligned.m8n8.x4.shared.b16 {%0,%1,%2,%3}, [%4];"
                 : "=r"(r[0]), "=r"(r[1]), "=r"(r[2]), "=r"(r[3]) : "r"(addr));
}
__device__ __forceinline__ void ldmatrix_x2t(uint32_t* r, uint32_t addr) {
    asm volatile("ldmatrix.sync.aligned.m8n8.x2.trans.shared.b16 {%0,%1}, [%2];"
                 : "=r"(r[0]), "=r"(r[1]) : "r"(addr));
}
__device__ __forceinline__ void mma_f16(float* c, const uint32_t* a, const uint32_t* b) {
    asm volatile(
        "mma.sync.aligned.m16n8k16.row.col.f32.f16.f16.f32 "
        "{%0,%1,%2,%3}, {%4,%5,%6,%7}, {%8,%9}, {%0,%1,%2,%3};"
        : "+f"(c[0]), "+f"(c[1]), "+f"(c[2]), "+f"(c[3])
        : "r"(a[0]), "r"(a[1]), "r"(a[2]), "r"(a[3]), "r"(b[0]), "r"(b[1]));
}
__device__ __forceinline__ void cp_async16(uint32_t dst, const void* src, int nbytes) {
    asm volatile("cp.async.ca.shared.global [%0], [%1], 16, %2;"
                 :: "r"(dst), "l"(src), "r"(nbytes));
}
__device__ __forceinline__ void cp_commit() {
    asm volatile("cp.async.commit_group;");
}
__device__ __forceinline__ void cp_wait2() {
    asm volatile("cp.async.wait_group 2;");
}

// ---------------- fp32 -> fp16 conversion (weights only; 8 elts/thread) ----------------
__global__ void conv_half_kernel(const float4* __restrict__ src,
                                 uint4* __restrict__ dst, int n8) {
    int i = blockIdx.x * blockDim.x + threadIdx.x;
    if (i >= n8) return;
    float4 a = __ldg(src + 2 * i);
    float4 b = __ldg(src + 2 * i + 1);
    uint4 o;
    ((__half2*)&o)[0] = __floats2half2_rn(a.x, a.y);
    ((__half2*)&o)[1] = __floats2half2_rn(a.z, a.w);
    ((__half2*)&o)[2] = __floats2half2_rn(b.x, b.y);
    ((__half2*)&o)[3] = __floats2half2_rn(b.z, b.w);
    dst[i] = o;
}

// ---------------- edge-index dtype detection ----------------
__global__ void detect_kernel(const int* __restrict__ ei_words) {
    if (threadIdx.x == 0 && blockIdx.x == 0) {
        int is64 = 1;
        #pragma unroll 1
        for (int i = 1; i < 512; i += 2)
            if (ei_words[i] != 0) { is64 = 0; break; }
        g_is64 = is64;
    }
}
__device__ __forceinline__ int edge_node(const void* ei, long long idx, int is64) {
    if (is64) return (int)((const long long*)ei)[idx];
    return ((const int*)ei)[idx];
}

// ---------------- CSR build ----------------
__global__ void zero_cnt_kernel() {
    int i = blockIdx.x * blockDim.x + threadIdx.x;
    if (i < N_NODES) g_cnt[i] = 0;
}
__global__ void hist_kernel(const void* __restrict__ ei) {
    int e = blockIdx.x * blockDim.x + threadIdx.x;
    if (e >= N_EDGES) return;
    int d = edge_node(ei, (long long)e + N_EDGES, g_is64);
    atomicAdd(&g_cnt[d], 1);
}
__global__ void dis_kernel() {
    int i = blockIdx.x * blockDim.x + threadIdx.x;
    if (i < N_NODES) g_dis[i] = rsqrtf((float)(g_cnt[i] + 1));
}
__global__ void scan1_kernel() {
    __shared__ int sh[256];
    int i = blockIdx.x * 256 + threadIdx.x;
    int v = (i < N_NODES) ? g_cnt[i] : 0;
    sh[threadIdx.x] = v;
    __syncthreads();
    #pragma unroll
    for (int off = 1; off < 256; off <<= 1) {
        int t = (threadIdx.x >= off) ? sh[threadIdx.x - off] : 0;
        __syncthreads();
        sh[threadIdx.x] += t;
        __syncthreads();
    }
    if (i < N_NODES) g_rowptr[i] = sh[threadIdx.x];
    if (threadIdx.x == 255) g_bsum[blockIdx.x] = sh[255];
}
__global__ void scan2_kernel() {
    __shared__ int sh[256];
    int v = (threadIdx.x < NBLK_SCAN) ? g_bsum[threadIdx.x] : 0;
    sh[threadIdx.x] = v;
    __syncthreads();
    #pragma unroll
    for (int off = 1; off < 256; off <<= 1) {
        int t = (threadIdx.x >= off) ? sh[threadIdx.x - off] : 0;
        __syncthreads();
        sh[threadIdx.x] += t;
        __syncthreads();
    }
    if (threadIdx.x < NBLK_SCAN) g_bsum[threadIdx.x] = sh[threadIdx.x] - v;
}
__global__ void scan3_kernel() {
    int i = blockIdx.x * 256 + threadIdx.x;
    if (i < N_NODES) {
        int ex = g_rowptr[i] - g_cnt[i] + g_bsum[blockIdx.x];
        g_rowptr[i] = ex;
        g_cur[i] = ex;
    }
}
__global__ void scatter_kernel(const void* __restrict__ ei) {
    int e = blockIdx.x * blockDim.x + threadIdx.x;
    if (e >= N_EDGES) return;
    int is64 = g_is64;
    int s = edge_node(ei, e, is64);
    int d = edge_node(ei, (long long)e + N_EDGES, is64);
    int pos = atomicAdd(&g_cur[d], 1);
    g_epack[pos] = make_float2(__int_as_float(s), g_dis[s] * g_dis[d]);
}

// ---------------- fp16 mma.sync GEMM, BM=128 BN=256 BK=16 ----------------
// 8 warps as 2(m) x 4(n); 64x64 per warp = 4x8 m16n8k16.
// A: register-staged (LDG -> [cvt] -> STS), 2-buffer; converts fp32->fp16 inline
//    when A_FP32 (fuses the x conversion into GEMM1).
// B: cp.async 4-stage pipeline (fp16 weights).
// As stride 24h (48B), Bs stride 264h (528B) — 16B-aligned, conflict-free.
template <bool USE_BIAS, bool OUT_HALF, bool A_FP32>
__global__ __launch_bounds__(256) void gemm_f16_kernel(
    const void* __restrict__ Av, const __half* __restrict__ B,
    const float* __restrict__ bias, void* __restrict__ Cv,
    int M, int N, int K)
{
    __shared__ __align__(16) __half As[2][128][24];
    __shared__ __align__(16) __half Bs[4][16][264];

    const int tid  = threadIdx.x;
    const int wid  = tid >> 5;
    const int lane = tid & 31;
    const int warp_m = wid & 1;
    const int warp_n = wid >> 1;         // 0..3
    const int rowBase = blockIdx.y * 128;
    const int colBase = blockIdx.x * 256;
    const int KT = K / 16;

    // ----- A staging: thread owns 8 halves: row ar, cols [ac, ac+8) -----
    const int ar = tid >> 1;             // 0..127
    const int ac = (tid & 1) * 8;        // 0 or 8
    const int a_row = (rowBase + ar < M) ? (rowBase + ar) : (M - 1);
    const bool a_ok = (rowBase + ar < M);
    const float*  a_src_f = (const float*)Av  + (size_t)a_row * K + ac;
    const __half* a_src_h = (const __half*)Av + (size_t)a_row * K + ac;

    const uint32_t as_base = smem_u32(&As[0][0][0]);
    const uint32_t bs_base = smem_u32(&Bs[0][0][0]);
    const uint32_t a_stage = 128 * 24 * 2;
    const uint32_t b_stage = 16 * 264 * 2;
    const uint32_t a_dst = as_base + (uint32_t)((ar * 24 + ac) * 2);

    uint4 regA;
    auto loadA = [&](int t) {
        if (A_FP32) {
            float4 f0 = a_ok ? __ldg((const float4*)(a_src_f + t * 16))     : make_float4(0,0,0,0);
            float4 f1 = a_ok ? __ldg((const float4*)(a_src_f + t * 16 + 4)) : make_float4(0,0,0,0);
            uint4 o;
            ((__half2*)&o)[0] = __floats2half2_rn(f0.x, f0.y);
            ((__half2*)&o)[1] = __floats2half2_rn(f0.z, f0.w);
            ((__half2*)&o)[2] = __floats2half2_rn(f1.x, f1.y);
            ((__half2*)&o)[3] = __floats2half2_rn(f1.z, f1.w);
            regA = o;
        } else {
            regA = a_ok ? __ldg((const uint4*)(a_src_h + t * 16)) : make_uint4(0,0,0,0);
        }
    };
    auto stsA = [&](int buf) {
        *(uint4*)((char*)nullptr + 0, (uint4*)0, (uint4*)0); // (unused; see below)
    };
    // (stsA defined inline below to avoid lambda address tricks)

    // ----- B staging: 2 chunks/thread per stage -----
    const int br0 = tid >> 5,         bc0 = (tid & 31) * 8;
    const int br1 = (tid + 256) >> 5, bc1 = ((tid + 256) & 31) * 8;
    const uint32_t b_dst0 = bs_base + (uint32_t)((br0 * 264 + bc0) * 2);
    const uint32_t b_dst1 = bs_base + (uint32_t)((br1 * 264 + bc1) * 2);
    const __half* b_src0 = B + (size_t)br0 * N + colBase + bc0;
    const __half* b_src1 = B + (size_t)br1 * N + colBase + bc1;

    auto issueB = [&](int s, int t) {
        cp_async16(b_dst0 + s * b_stage, b_src0 + (size_t)t * 16 * N, 16);
        cp_async16(b_dst1 + s * b_stage, b_src1 + (size_t)t * 16 * N, 16);
    };

    float acc[4][8][4];
    #pragma unroll
    for (int i = 0; i < 4; i++)
        #pragma unroll
        for (int j = 0; j < 8; j++)
            #pragma unroll
            for (int r = 0; r < 4; r++) acc[i][j][r] = 0.f;

    // fragment ldmatrix addresses
    uint32_t a_off[4], b_off[8];
    {
        const int arow = lane & 15;
        const int acol = (lane >> 4) * 8;
        #pragma unroll
        for (int i = 0; i < 4; i++)
            a_off[i] = as_base + (uint32_t)(((warp_m * 64 + i * 16 + arow) * 24 + acol) * 2);
        #pragma unroll
        for (int j = 0; j < 8; j++)
            b_off[j] = bs_base + (uint32_t)(((lane & 15) * 264 + warp_n * 64 + j * 8) * 2);
    }

    // prologue: A tile0 -> smem buf0; A tile1 -> regs; B stages 0..2 in flight
    loadA(0);
    *(uint4*)&As[0][ar][ac] = regA;
    if (KT > 1) loadA(1);
    #pragma unroll
    for (int s = 0; s < 3; s++) { issueB(s, s); cp_commit(); }

    for (int t = 0; t < KT; t++) {
        cp_wait2();
        __syncthreads();
        if (t + 3 < KT) issueB((t + 3) & 3, t + 3);
        cp_commit();

        const int abuf = t & 1;
        const int bbuf = t & 3;
        uint32_t af[4][4];
        #pragma unroll
        for (int i = 0; i < 4; i++) ldmatrix_x4(af[i], a_off[i] + abuf * a_stage);

        #pragma unroll
        for (int jb = 0; jb < 2; jb++) {
            uint32_t bf[4][2];
            #pragma unroll
            for (int jj = 0; jj < 4; jj++)
                ldmatrix_x2t(bf[jj], b_off[jb * 4 + jj] + bbuf * b_stage);
            #pragma unroll
            for (int i = 0; i < 4; i++)
                #pragma unroll
                for (int jj = 0; jj < 4; jj++)
                    mma_f16(acc[i][jb * 4 + jj], af[i], bf[jj]);
        }

        // stage A for tile t+1 (write the buffer consumed at t-1; safe past top sync)
        if (t + 1 < KT) {
            *(uint4*)&As[(t + 1) & 1][ar][ac] = regA;
            if (t + 2 < KT) loadA(t + 2);
        }
    }

    const int lg = lane >> 2;
    const int lr = lane & 3;
    #pragma unroll
    for (int i = 0; i < 4; i++) {
        const int r0 = rowBase + warp_m * 64 + i * 16 + lg;
        #pragma unroll
        for (int half = 0; half < 2; half++) {
            const int rr = r0 + half * 8;
            if (rr >= M) continue;
            #pragma unroll
            for (int j = 0; j < 8; j++) {
                const int cc = colBase + warp_n * 64 + j * 8 + lr * 2;
                float v0 = acc[i][j][half * 2 + 0];
                float v1 = acc[i][j][half * 2 + 1];
                if (USE_BIAS) { v0 += bias[cc]; v1 += bias[cc + 1]; }
                if (OUT_HALF) {
                    __half2* C = (__half2*)Cv;
                    C[((size_t)rr * N + cc) >> 1] = __floats2half2_rn(v0, v1);
                } else {
                    float* C = (float*)Cv;
                    *(float2*)(C + (size_t)rr * N + cc) = make_float2(v0, v1);
                }
            }
        }
    }
}

// ---------------- CSR gather aggregation (fp16 in, fp32 accumulate, fp16 out) ----------------
template <bool L1>
__global__ __launch_bounds__(256) void gather_kernel(
    const __half* __restrict__ srcfeat,
    const float* __restrict__ bias,
    __half* __restrict__ out)
{
    __shared__ float2 se[8][32];
    const int w    = threadIdx.x >> 5;
    const int warp = blockIdx.x * 8 + w;
    const int lane = threadIdx.x & 31;
    if (warp >= N_NODES) return;

    const int start = g_rowptr[warp];
    const int end   = start + g_cnt[warp];
    const float di  = g_dis[warp];
    const float nn  = di * di;

    float acc[8];

    // self term
    {
        uint4 raw = __ldg((const uint4*)(srcfeat + (size_t)warp * MID_DIM) + lane);
        const __half2* hp = (const __half2*)&raw;
        #pragma unroll
        for (int q = 0; q < 4; q++) {
            float2 f = __half22float2(hp[q]);
            acc[2 * q]     = f.x * nn;
            acc[2 * q + 1] = f.y * nn;
        }
    }

    // edges: stage 32 records in smem, LDS broadcast per edge
    for (int base = start; base < end; base += 32) {
        const int rem = min(32, end - base);
        if (base + lane < end) se[w][lane] = __ldg(&g_epack[base + lane]);
        __syncwarp();
        #pragma unroll 4
        for (int j = 0; j < rem; j++) {
            const float2 e = se[w][j];
            const int   s  = __float_as_int(e.x);
            const float wt = e.y;
            uint4 raw = __ldg((const uint4*)(srcfeat + (size_t)s * MID_DIM) + lane);
            const __half2* hp = (const __half2*)&raw;
            #pragma unroll
            for (int q = 0; q < 4; q++) {
                float2 f = __half22float2(hp[q]);
                acc[2 * q]     = fmaf(wt, f.x, acc[2 * q]);
                acc[2 * q + 1] = fmaf(wt, f.y, acc[2 * q + 1]);
            }
        }
        __syncwarp();
    }

    uint4 outv;
    __half2* op = (__half2*)&outv;
    if (L1) {
        const int c8 = lane * 8;
        float4 bb0 = *(const float4*)(bias + c8);
        float4 bb1 = *(const float4*)(bias + c8 + 4);
        float b[8] = {bb0.x, bb0.y, bb0.z, bb0.w, bb1.x, bb1.y, bb1.z, bb1.w};
        #pragma unroll
        for (int q = 0; q < 4; q++) {
            float v0 = fmaxf(acc[2 * q]     + b[2 * q],     0.f);
            float v1 = fmaxf(acc[2 * q + 1] + b[2 * q + 1], 0.f);
            op[q] = __floats2half2_rn(v0, v1);
        }
    } else {
        #pragma unroll
        for (int q = 0; q < 4; q++)
            op[q] = __floats2half2_rn(acc[2 * q], acc[2 * q + 1]);
    }
    ((uint4*)(out + (size_t)warp * MID_DIM))[lane] = outv;
}

// ---------------- launch ----------------
extern "C" void kernel_launch(void* const* d_in, const int* in_sizes, int n_in,
                              void* d_out, int out_size)
{
    const float* x  = (const float*)d_in[0];
    const void*  ei = d_in[1];
    const float* W1 = (const float*)d_in[2];
    const float* b1 = (const float*)d_in[3];
    const float* W2 = (const float*)d_in[4];
    const float* b2 = (const float*)d_in[5];
    float* out = (float*)d_out;

    __half *w1h, *w2h, *xw, *h, *ag2;
    cudaGetSymbolAddress((void**)&w1h, g_w1h);
    cudaGetSymbolAddress((void**)&w2h, g_w2h);
    cudaGetSymbolAddress((void**)&xw,  g_xw);
    cudaGetSymbolAddress((void**)&h,   g_h);
    cudaGetSymbolAddress((void**)&ag2, g_ag2);

    const int nb_nodes = (N_NODES + 255) / 256;
    const int nb_edges = (N_EDGES + 255) / 256;
    const int mblocks = (N_NODES + 127) / 128;
    const int gblocks = (N_NODES + 7) / 8;

    // 1-3: weight fp16 conversions + edge dtype detection
    {
        int n8w = (IN_DIM * MID_DIM) / 8;
        conv_half_kernel<<<(n8w + 255) / 256, 256>>>((const float4*)W1, (uint4*)w1h, n8w);
        conv_half_kernel<<<(n8w + 255) / 256, 256>>>((const float4*)W2, (uint4*)w2h, n8w);
    }
    detect_kernel<<<1, 32>>>((const int*)ei);

    // 4 (ncu capture slot): GEMM1 xw = x@W1 (fp32 A converted in-kernel, fp16 out)
    gemm_f16_kernel<false, true, true><<<dim3(MID_DIM / 256, mblocks), 256>>>(
        x, w1h, nullptr, xw, N_NODES, MID_DIM, IN_DIM);

    // CSR build
    zero_cnt_kernel<<<nb_nodes, 256>>>();
    hist_kernel<<<nb_edges, 256>>>(ei);
    dis_kernel<<<nb_nodes, 256>>>();
    scan1_kernel<<<NBLK_SCAN, 256>>>();
    scan2_kernel<<<1, 256>>>();
    scan3_kernel<<<NBLK_SCAN, 256>>>();
    scatter_kernel<<<nb_edges, 256>>>(ei);

    // layer 1 aggregation: h = relu(A_norm xw + b1)
    gather_kernel<true><<<gblocks, 256>>>(xw, b1, h);

    // layer 2: ag2 = A_norm h ; out = ag2@W2 + b2
    gather_kernel<false><<<gblocks, 256>>>(h, nullptr, ag2);
    gemm_f16_kernel<true, false, false><<<dim3(IN_DIM / 256, mblocks), 256>>>(
        ag2, w2h, b2, out, N_NODES, IN_DIM, MID_DIM);
}

// round 12
// speedup vs baseline: 1.4684x; 1.4684x over previous
#include <cuda_runtime.h>
#include <cuda_fp16.h>
#include <cstdint>

#define N_NODES 50000
#define N_EDGES 1600000
#define IN_DIM  1024
#define MID_DIM 256
#define NBLK_SCAN ((N_NODES + 255) / 256)   // 196

// ---------------- scratch (device globals; no allocs allowed) ----------------
__device__ __align__(16) float  g_dis[N_NODES];
__device__ __align__(16) __half g_w1h [(size_t)IN_DIM * MID_DIM];   // fp16(W1)
__device__ __align__(16) __half g_w2h [(size_t)MID_DIM * IN_DIM];   // fp16(W2)
__device__ __align__(16) __half g_xw  [(size_t)N_NODES * MID_DIM];  // x@W1
__device__ __align__(16) __half g_h   [(size_t)N_NODES * MID_DIM];  // relu(A xw + b1)
__device__ __align__(16) __half g_ag2 [(size_t)N_NODES * MID_DIM];  // A h
__device__ int    g_cnt[N_NODES];
__device__ int    g_rowptr[N_NODES];
__device__ int    g_cur[N_NODES];
__device__ int    g_bsum[NBLK_SCAN];
__device__ __align__(8) float2 g_epack[N_EDGES];  // {src_as_float_bits, norm}
__device__ int    g_is64;

// ---------------- helpers ----------------
__device__ __forceinline__ uint32_t smem_u32(const void* p) {
    uint32_t a;
    asm("{ .reg .u64 t; cvta.to.shared.u64 t, %1; cvt.u32.u64 %0, t; }"
        : "=r"(a) : "l"(p));
    return a;
}
__device__ __forceinline__ void ldmatrix_x4(uint32_t* r, uint32_t addr) {
    asm volatile("ldmatrix.sync.aligned.m8n8.x4.shared.b16 {%0,%1,%2,%3}, [%4];"
                 : "=r"(r[0]), "=r"(r[1]), "=r"(r[2]), "=r"(r[3]) : "r"(addr));
}
__device__ __forceinline__ void ldmatrix_x2t(uint32_t* r, uint32_t addr) {
    asm volatile("ldmatrix.sync.aligned.m8n8.x2.trans.shared.b16 {%0,%1}, [%2];"
                 : "=r"(r[0]), "=r"(r[1]) : "r"(addr));
}
__device__ __forceinline__ void mma_f16(float* c, const uint32_t* a, const uint32_t* b) {
    asm volatile(
        "mma.sync.aligned.m16n8k16.row.col.f32.f16.f16.f32 "
        "{%0,%1,%2,%3}, {%4,%5,%6,%7}, {%8,%9}, {%0,%1,%2,%3};"
        : "+f"(c[0]), "+f"(c[1]), "+f"(c[2]), "+f"(c[3])
        : "r"(a[0]), "r"(a[1]), "r"(a[2]), "r"(a[3]), "r"(b[0]), "r"(b[1]));
}
__device__ __forceinline__ void cp_async16(uint32_t dst, const void* src, int nbytes) {
    asm volatile("cp.async.ca.shared.global [%0], [%1], 16, %2;"
                 :: "r"(dst), "l"(src), "r"(nbytes));
}
__device__ __forceinline__ void cp_commit() {
    asm volatile("cp.async.commit_group;");
}
__device__ __forceinline__ void cp_wait2() {
    asm volatile("cp.async.wait_group 2;");
}

// ---------------- fp32 -> fp16 conversion (weights only; 8 elts/thread) ----------------
__global__ void conv_half_kernel(const float4* __restrict__ src,
                                 uint4* __restrict__ dst, int n8) {
    int i = blockIdx.x * blockDim.x + threadIdx.x;
    if (i >= n8) return;
    float4 a = __ldg(src + 2 * i);
    float4 b = __ldg(src + 2 * i + 1);
    uint4 o;
    ((__half2*)&o)[0] = __floats2half2_rn(a.x, a.y);
    ((__half2*)&o)[1] = __floats2half2_rn(a.z, a.w);
    ((__half2*)&o)[2] = __floats2half2_rn(b.x, b.y);
    ((__half2*)&o)[3] = __floats2half2_rn(b.z, b.w);
    dst[i] = o;
}

// ---------------- edge-index dtype detection ----------------
__global__ void detect_kernel(const int* __restrict__ ei_words) {
    if (threadIdx.x == 0 && blockIdx.x == 0) {
        int is64 = 1;
        #pragma unroll 1
        for (int i = 1; i < 512; i += 2)
            if (ei_words[i] != 0) { is64 = 0; break; }
        g_is64 = is64;
    }
}
__device__ __forceinline__ int edge_node(const void* ei, long long idx, int is64) {
    if (is64) return (int)((const long long*)ei)[idx];
    return ((const int*)ei)[idx];
}

// ---------------- CSR build ----------------
__global__ void zero_cnt_kernel() {
    int i = blockIdx.x * blockDim.x + threadIdx.x;
    if (i < N_NODES) g_cnt[i] = 0;
}
__global__ void hist_kernel(const void* __restrict__ ei) {
    int e = blockIdx.x * blockDim.x + threadIdx.x;
    if (e >= N_EDGES) return;
    int d = edge_node(ei, (long long)e + N_EDGES, g_is64);
    atomicAdd(&g_cnt[d], 1);
}
__global__ void dis_kernel() {
    int i = blockIdx.x * blockDim.x + threadIdx.x;
    if (i < N_NODES) g_dis[i] = rsqrtf((float)(g_cnt[i] + 1));
}
__global__ void scan1_kernel() {
    __shared__ int sh[256];
    int i = blockIdx.x * 256 + threadIdx.x;
    int v = (i < N_NODES) ? g_cnt[i] : 0;
    sh[threadIdx.x] = v;
    __syncthreads();
    #pragma unroll
    for (int off = 1; off < 256; off <<= 1) {
        int t = (threadIdx.x >= off) ? sh[threadIdx.x - off] : 0;
        __syncthreads();
        sh[threadIdx.x] += t;
        __syncthreads();
    }
    if (i < N_NODES) g_rowptr[i] = sh[threadIdx.x];
    if (threadIdx.x == 255) g_bsum[blockIdx.x] = sh[255];
}
__global__ void scan2_kernel() {
    __shared__ int sh[256];
    int v = (threadIdx.x < NBLK_SCAN) ? g_bsum[threadIdx.x] : 0;
    sh[threadIdx.x] = v;
    __syncthreads();
    #pragma unroll
    for (int off = 1; off < 256; off <<= 1) {
        int t = (threadIdx.x >= off) ? sh[threadIdx.x - off] : 0;
        __syncthreads();
        sh[threadIdx.x] += t;
        __syncthreads();
    }
    if (threadIdx.x < NBLK_SCAN) g_bsum[threadIdx.x] = sh[threadIdx.x] - v;
}
__global__ void scan3_kernel() {
    int i = blockIdx.x * 256 + threadIdx.x;
    if (i < N_NODES) {
        int ex = g_rowptr[i] - g_cnt[i] + g_bsum[blockIdx.x];
        g_rowptr[i] = ex;
        g_cur[i] = ex;
    }
}
__global__ void scatter_kernel(const void* __restrict__ ei) {
    int e = blockIdx.x * blockDim.x + threadIdx.x;
    if (e >= N_EDGES) return;
    int is64 = g_is64;
    int s = edge_node(ei, e, is64);
    int d = edge_node(ei, (long long)e + N_EDGES, is64);
    int pos = atomicAdd(&g_cur[d], 1);
    g_epack[pos] = make_float2(__int_as_float(s), g_dis[s] * g_dis[d]);
}

// ---------------- fp16 mma.sync GEMM, BM=128 BN=256 BK=16 ----------------
// 8 warps as 2(m) x 4(n); 64x64 per warp = 4x8 m16n8k16.
// B: cp.async 4-stage pipeline (fp16 weights).
// A, A_FP32=false: cp.async 4-stage (fp16 GMEM) — R9 schedule.
// A, A_FP32=true : LDG fp32 + cvt + STS, 4 SMEM stages, 3-deep register
//                  pipeline (rA0=tile t+1, rA1=tile t+2; LDG t+3 each iter)
//                  — fuses the x fp32->fp16 conversion into GEMM1.
// As stride 24h (48B), Bs stride 264h (528B) — 16B-aligned, conflict-free.
template <bool USE_BIAS, bool OUT_HALF, bool A_FP32>
__global__ __launch_bounds__(256) void gemm_f16_kernel(
    const void* __restrict__ Av, const __half* __restrict__ B,
    const float* __restrict__ bias, void* __restrict__ Cv,
    int M, int N, int K)
{
    __shared__ __align__(16) __half As[4][128][24];
    __shared__ __align__(16) __half Bs[4][16][264];

    const int tid  = threadIdx.x;
    const int wid  = tid >> 5;
    const int lane = tid & 31;
    const int warp_m = wid & 1;
    const int warp_n = wid >> 1;         // 0..3
    const int rowBase = blockIdx.y * 128;
    const int colBase = blockIdx.x * 256;
    const int KT = K / 16;

    // ----- A staging: thread owns 8 halves: row ar, cols [ac, ac+8) -----
    const int ar = tid >> 1;             // 0..127
    const int ac = (tid & 1) * 8;        // 0 or 8
    const bool a_ok = (rowBase + ar < M);
    const int a_row = a_ok ? (rowBase + ar) : (M - 1);
    const float*  a_src_f = (const float*)Av  + (size_t)a_row * K + ac;
    const __half* a_src_h = (const __half*)Av + (size_t)a_row * K + ac;

    const uint32_t as_base = smem_u32(&As[0][0][0]);
    const uint32_t bs_base = smem_u32(&Bs[0][0][0]);
    const uint32_t a_stage = 128 * 24 * 2;
    const uint32_t b_stage = 16 * 264 * 2;
    const uint32_t a_dst = as_base + (uint32_t)((ar * 24 + ac) * 2);

    auto loadA_cvt = [&](int t) -> uint4 {
        float4 f0 = a_ok ? __ldg((const float4*)(a_src_f + t * 16))     : make_float4(0,0,0,0);
        float4 f1 = a_ok ? __ldg((const float4*)(a_src_f + t * 16 + 4)) : make_float4(0,0,0,0);
        uint4 o;
        ((__half2*)&o)[0] = __floats2half2_rn(f0.x, f0.y);
        ((__half2*)&o)[1] = __floats2half2_rn(f0.z, f0.w);
        ((__half2*)&o)[2] = __floats2half2_rn(f1.x, f1.y);
        ((__half2*)&o)[3] = __floats2half2_rn(f1.z, f1.w);
        return o;
    };

    // ----- B staging: 2 chunks/thread per stage -----
    const int br0 = tid >> 5,         bc0 = (tid & 31) * 8;
    const int br1 = (tid + 256) >> 5, bc1 = ((tid + 256) & 31) * 8;
    const uint32_t b_dst0 = bs_base + (uint32_t)((br0 * 264 + bc0) * 2);
    const uint32_t b_dst1 = bs_base + (uint32_t)((br1 * 264 + bc1) * 2);
    const __half* b_src0 = B + (size_t)br0 * N + colBase + bc0;
    const __half* b_src1 = B + (size_t)br1 * N + colBase + bc1;

    auto issueB = [&](int s, int t) {
        cp_async16(b_dst0 + s * b_stage, b_src0 + (size_t)t * 16 * N, 16);
        cp_async16(b_dst1 + s * b_stage, b_src1 + (size_t)t * 16 * N, 16);
    };
    auto issueA_cp = [&](int s, int t) {
        cp_async16(a_dst + s * a_stage, a_src_h + t * 16, a_ok ? 16 : 0);
    };

    float acc[4][8][4];
    #pragma unroll
    for (int i = 0; i < 4; i++)
        #pragma unroll
        for (int j = 0; j < 8; j++)
            #pragma unroll
            for (int r = 0; r < 4; r++) acc[i][j][r] = 0.f;

    // fragment ldmatrix addresses
    uint32_t a_off[4], b_off[8];
    {
        const int arow = lane & 15;
        const int acol = (lane >> 4) * 8;
        #pragma unroll
        for (int i = 0; i < 4; i++)
            a_off[i] = as_base + (uint32_t)(((warp_m * 64 + i * 16 + arow) * 24 + acol) * 2);
        #pragma unroll
        for (int j = 0; j < 8; j++)
            b_off[j] = bs_base + (uint32_t)(((lane & 15) * 264 + warp_n * 64 + j * 8) * 2);
    }

    // ----- prologue -----
    uint4 rA0 = make_uint4(0,0,0,0), rA1 = make_uint4(0,0,0,0);
    if (A_FP32) {
        uint4 t0 = loadA_cvt(0);
        *(uint4*)&As[0][ar][ac] = t0;              // tile 0 staged
        if (KT > 1) rA0 = loadA_cvt(1);            // tile 1
        if (KT > 2) rA1 = loadA_cvt(2);            // tile 2
    }
    #pragma unroll
    for (int s = 0; s < 3; s++) {
        if (!A_FP32 && s < KT) issueA_cp(s, s);
        if (s < KT) issueB(s, s);
        cp_commit();
    }

    for (int t = 0; t < KT; t++) {
        cp_wait2();
        __syncthreads();
        if (t + 3 < KT) {
            if (!A_FP32) issueA_cp((t + 3) & 3, t + 3);
            issueB((t + 3) & 3, t + 3);
        }
        cp_commit();

        const int buf = t & 3;
        uint32_t af[4][4];
        #pragma unroll
        for (int i = 0; i < 4; i++) ldmatrix_x4(af[i], a_off[i] + buf * a_stage);

        #pragma unroll
        for (int jb = 0; jb < 2; jb++) {
            uint32_t bf[4][2];
            #pragma unroll
            for (int jj = 0; jj < 4; jj++)
                ldmatrix_x2t(bf[jj], b_off[jb * 4 + jj] + buf * b_stage);
            #pragma unroll
            for (int i = 0; i < 4; i++)
                #pragma unroll
                for (int jj = 0; jj < 4; jj++)
                    mma_f16(acc[i][jb * 4 + jj], af[i], bf[jj]);
        }

        if (A_FP32) {
            // STS tile t+1 (buffer (t+1)&3 was last read at iter t-3; safe past top sync)
            if (t + 1 < KT) *(uint4*)&As[(t + 1) & 3][ar][ac] = rA0;
            rA0 = rA1;
            if (t + 3 < KT) rA1 = loadA_cvt(t + 3);   // ~2 iterations to land
        }
    }

    const int lg = lane >> 2;
    const int lr = lane & 3;
    #pragma unroll
    for (int i = 0; i < 4; i++) {
        const int r0 = rowBase + warp_m * 64 + i * 16 + lg;
        #pragma unroll
        for (int half = 0; half < 2; half++) {
            const int rr = r0 + half * 8;
            if (rr >= M) continue;
            #pragma unroll
            for (int j = 0; j < 8; j++) {
                const int cc = colBase + warp_n * 64 + j * 8 + lr * 2;
                float v0 = acc[i][j][half * 2 + 0];
                float v1 = acc[i][j][half * 2 + 1];
                if (USE_BIAS) { v0 += bias[cc]; v1 += bias[cc + 1]; }
                if (OUT_HALF) {
                    __half2* C = (__half2*)Cv;
                    C[((size_t)rr * N + cc) >> 1] = __floats2half2_rn(v0, v1);
                } else {
                    float* C = (float*)Cv;
                    *(float2*)(C + (size_t)rr * N + cc) = make_float2(v0, v1);
                }
            }
        }
    }
}

// ---------------- CSR gather aggregation (fp16 in, fp32 accumulate, fp16 out) ----------------
template <bool L1>
__global__ __launch_bounds__(256) void gather_kernel(
    const __half* __restrict__ srcfeat,
    const float* __restrict__ bias,
    __half* __restrict__ out)
{
    __shared__ float2 se[8][32];
    const int w    = threadIdx.x >> 5;
    const int warp = blockIdx.x * 8 + w;
    const int lane = threadIdx.x & 31;
    if (warp >= N_NODES) return;

    const int start = g_rowptr[warp];
    const int end   = start + g_cnt[warp];
    const float di  = g_dis[warp];
    const float nn  = di * di;

    float acc[8];

    // self term
    {
        uint4 raw = __ldg((const uint4*)(srcfeat + (size_t)warp * MID_DIM) + lane);
        const __half2* hp = (const __half2*)&raw;
        #pragma unroll
        for (int q = 0; q < 4; q++) {
            float2 f = __half22float2(hp[q]);
            acc[2 * q]     = f.x * nn;
            acc[2 * q + 1] = f.y * nn;
        }
    }

    // edges: stage 32 records in smem, LDS broadcast per edge
    for (int base = start; base < end; base += 32) {
        const int rem = min(32, end - base);
        if (base + lane < end) se[w][lane] = __ldg(&g_epack[base + lane]);
        __syncwarp();
        #pragma unroll 4
        for (int j = 0; j < rem; j++) {
            const float2 e = se[w][j];
            const int   s  = __float_as_int(e.x);
            const float wt = e.y;
            uint4 raw = __ldg((const uint4*)(srcfeat + (size_t)s * MID_DIM) + lane);
            const __half2* hp = (const __half2*)&raw;
            #pragma unroll
            for (int q = 0; q < 4; q++) {
                float2 f = __half22float2(hp[q]);
                acc[2 * q]     = fmaf(wt, f.x, acc[2 * q]);
                acc[2 * q + 1] = fmaf(wt, f.y, acc[2 * q + 1]);
            }
        }
        __syncwarp();
    }

    uint4 outv;
    __half2* op = (__half2*)&outv;
    if (L1) {
        const int c8 = lane * 8;
        float4 bb0 = *(const float4*)(bias + c8);
        float4 bb1 = *(const float4*)(bias + c8 + 4);
        float b[8] = {bb0.x, bb0.y, bb0.z, bb0.w, bb1.x, bb1.y, bb1.z, bb1.w};
        #pragma unroll
        for (int q = 0; q < 4; q++) {
            float v0 = fmaxf(acc[2 * q]     + b[2 * q],     0.f);
            float v1 = fmaxf(acc[2 * q + 1] + b[2 * q + 1], 0.f);
            op[q] = __floats2half2_rn(v0, v1);
        }
    } else {
        #pragma unroll
        for (int q = 0; q < 4; q++)
            op[q] = __floats2half2_rn(acc[2 * q], acc[2 * q + 1]);
    }
    ((uint4*)(out + (size_t)warp * MID_DIM))[lane] = outv;
}

// ---------------- launch ----------------
extern "C" void kernel_launch(void* const* d_in, const int* in_sizes, int n_in,
                              void* d_out, int out_size)
{
    const float* x  = (const float*)d_in[0];
    const void*  ei = d_in[1];
    const float* W1 = (const float*)d_in[2];
    const float* b1 = (const float*)d_in[3];
    const float* W2 = (const float*)d_in[4];
    const float* b2 = (const float*)d_in[5];
    float* out = (float*)d_out;

    __half *w1h, *w2h, *xw, *h, *ag2;
    cudaGetSymbolAddress((void**)&w1h, g_w1h);
    cudaGetSymbolAddress((void**)&w2h, g_w2h);
    cudaGetSymbolAddress((void**)&xw,  g_xw);
    cudaGetSymbolAddress((void**)&h,   g_h);
    cudaGetSymbolAddress((void**)&ag2, g_ag2);

    const int nb_nodes = (N_NODES + 255) / 256;
    const int nb_edges = (N_EDGES + 255) / 256;
    const int mblocks = (N_NODES + 127) / 128;
    const int gblocks = (N_NODES + 7) / 8;

    // 1-3: weight fp16 conversions + edge dtype detection
    {
        int n8w = (IN_DIM * MID_DIM) / 8;
        conv_half_kernel<<<(n8w + 255) / 256, 256>>>((const float4*)W1, (uint4*)w1h, n8w);
        conv_half_kernel<<<(n8w + 255) / 256, 256>>>((const float4*)W2, (uint4*)w2h, n8w);
    }
    detect_kernel<<<1, 32>>>((const int*)ei);

    // 4 (ncu capture slot): GEMM1 xw = x@W1 (fp32 A converted in-kernel, fp16 out)
    gemm_f16_kernel<false, true, true><<<dim3(MID_DIM / 256, mblocks), 256>>>(
        x, w1h, nullptr, xw, N_NODES, MID_DIM, IN_DIM);

    // CSR build
    zero_cnt_kernel<<<nb_nodes, 256>>>();
    hist_kernel<<<nb_edges, 256>>>(ei);
    dis_kernel<<<nb_nodes, 256>>>();
    scan1_kernel<<<NBLK_SCAN, 256>>>();
    scan2_kernel<<<1, 256>>>();
    scan3_kernel<<<NBLK_SCAN, 256>>>();
    scatter_kernel<<<nb_edges, 256>>>(ei);

    // layer 1 aggregation: h = relu(A_norm xw + b1)
    gather_kernel<true><<<gblocks, 256>>>(xw, b1, h);

    // layer 2: ag2 = A_norm h ; out = ag2@W2 + b2
    gather_kernel<false><<<gblocks, 256>>>(h, nullptr, ag2);
    gemm_f16_kernel<true, false, false><<<dim3(IN_DIM / 256, mblocks), 256>>>(
        ag2, w2h, b2, out, N_NODES, IN_DIM, MID_DIM);
}